// round 16
// baseline (speedup 1.0000x reference)
#include <cuda_runtime.h>
#include <cuda_fp16.h>
#include <math.h>
#include <stdint.h>

#define N_NODES 50000
#define N_EDGES 800000
#define NB      250
#define NT      8
#define C_IN    32
#define C_OUT   64
#define NPG     200   // nodes per graph (contiguous)
#define SCAN_NBLK ((N_NODES + 255) / 256)   // 196

// ---------------- scratch (static device globals; no allocation) -------------
__device__ __half g_xh[(size_t)N_NODES * NT * C_IN];    // [n][t][c] fp16 (row 512B)
__device__ __half g_hA[(size_t)N_NODES * NT * C_OUT];   // ping
__device__ __half g_hB[(size_t)N_NODES * NT * C_OUT];   // pong
__device__ uint2  g_Wf1[2 * 8 * 32];   // W1 MMA fragments [ks][j][lane]
__device__ uint2  g_Wf2[4 * 8 * 32];
__device__ uint2  g_Wf3[4 * 8 * 32];
__device__ int    g_deg[N_NODES];      // zero-init at load; re-zeroed by fused<32>
__device__ int    g_cnt[N_NODES];
__device__ int    g_rowptr[N_NODES + 1];
__device__ int    g_bsum[SCAN_NBLK];
__device__ float  g_dinv[N_NODES];
__device__ uint2  g_edge[N_EDGES];     // {src, norm bits}

// ---------------- helpers ----------------------------------------------------
__device__ __forceinline__ float2 u2f(uint32_t u) {
    __half2 h = *(__half2*)&u;
    return __half22float2(h);
}
__device__ __forceinline__ uint32_t f2u(float a, float b) {
    __half2 h = __floats2half2_rn(a, b);
    return *(uint32_t*)&h;
}

// ---------------- setup: W frags + transpose x + count_deg -------------------
__device__ __forceinline__ void wfrag_store(uint2* Wf, const float* W, int rem) {
    int ks = rem >> 8, j = (rem >> 5) & 7, lane = rem & 31;
    int lq = lane >> 2, lr = lane & 3;
    int n = j * 8 + lq;
    int kb = ks * 16 + lr * 2;
    uint2 f;
    f.x = f2u(W[kb * 64 + n],       W[(kb + 1) * 64 + n]);
    f.y = f2u(W[(kb + 8) * 64 + n], W[(kb + 9) * 64 + n]);
    Wf[rem] = f;
}

__global__ void setup_all_kernel(const float* __restrict__ x,
                                 const int* __restrict__ ei,
                                 const float* __restrict__ W1,
                                 const float* __restrict__ W2,
                                 const float* __restrict__ W3) {
    int i = blockIdx.x * blockDim.x + threadIdx.x;
    if (i < 512)                    wfrag_store(g_Wf1, W1, i);
    else if (i >= 1024 && i < 2048) wfrag_store(g_Wf2, W2, i - 1024);
    else if (i >= 2048 && i < 3072) wfrag_store(g_Wf3, W3, i - 2048);
    if (i < N_EDGES) {
        int dst = ei[N_EDGES + i];
        if ((unsigned)dst < (unsigned)N_NODES)
            atomicAdd(&g_deg[dst], 1);
    }
    if (i >= N_NODES * C_IN) return;
    int n = i / C_IN, c = i % C_IN;
    const float4* p = (const float4*)(x + (size_t)i * NT);
    float4 a = p[0], b4 = p[1];
    float v[8] = {a.x, a.y, a.z, a.w, b4.x, b4.y, b4.z, b4.w};
#pragma unroll
    for (int t = 0; t < NT; t++)
        g_xh[(size_t)n * (NT * C_IN) + t * C_IN + c] = __float2half_rn(v[t]);
}

// ---------------- parallel scan ---------------------------------------------
__global__ void __launch_bounds__(256) scan_part_kernel() {
    __shared__ int ws[8];
    int b = blockIdx.x, tid = threadIdx.x;
    int i = b * 256 + tid;
    int lane = tid & 31, wid = tid >> 5;
    int v = (i < N_NODES) ? g_deg[i] : 0;
    if (i < N_NODES) g_dinv[i] = rsqrtf((float)(v + 1));  // +1 self loop
    int x = v;
#pragma unroll
    for (int off = 1; off < 32; off <<= 1) {
        int y = __shfl_up_sync(0xffffffffu, x, off);
        if (lane >= off) x += y;
    }
    if (lane == 31) ws[wid] = x;
    __syncthreads();
    if (tid < 8) {
        int s = ws[tid];
#pragma unroll
        for (int off = 1; off < 8; off <<= 1) {
            int y = __shfl_up_sync(0x000000ffu, s, off);
            if (tid >= off) s += y;
        }
        ws[tid] = s;
    }
    __syncthreads();
    int woff = wid ? ws[wid - 1] : 0;
    if (i < N_NODES) g_rowptr[i] = woff + x - v;   // local exclusive
    if (tid == 0) g_bsum[b] = ws[7];
}

// grid 49 x 1024: each block redundantly scans the 196 block sums, then
// applies offsets to its range. Cross-warp smem edges use __syncthreads.
__global__ void __launch_bounds__(1024) scan_apply_kernel() {
    __shared__ int boff[256];
    __shared__ int wsum[8];
    int tid = threadIdx.x;
    int lane = tid & 31, wid = tid >> 5;
    int v = 0, x = 0;
    if (tid < 256) {
        v = (tid < SCAN_NBLK) ? g_bsum[tid] : 0;
        x = v;
#pragma unroll
        for (int off = 1; off < 32; off <<= 1) {
            int y = __shfl_up_sync(0xffffffffu, x, off);
            if (lane >= off) x += y;
        }
        if (lane == 31) wsum[wid] = x;
    }
    __syncthreads();
    if (tid == 0) {
        int run = 0;
#pragma unroll
        for (int w = 0; w < 8; w++) { int s = wsum[w]; wsum[w] = run; run += s; }
        if (blockIdx.x == 0) g_rowptr[N_NODES] = run;
    }
    __syncthreads();
    if (tid < 256)
        boff[tid] = wsum[wid] + x - v;
    __syncthreads();
    int i = blockIdx.x * 1024 + tid;
    if (i < N_NODES) g_rowptr[i] += boff[i >> 8];
}

// 4 edges per thread: 4 independent atomic->store chains in flight (ILP=4).
#define FILL_EPT 4
__global__ void __launch_bounds__(256) fill_csr_kernel(const int* __restrict__ ei) {
    int t0 = (blockIdx.x * 256 + threadIdx.x) * FILL_EPT;
    int srcv[FILL_EPT], dstv[FILL_EPT], posv[FILL_EPT];
    bool ok[FILL_EPT];
#pragma unroll
    for (int k = 0; k < FILL_EPT; k++) {
        int e = t0 + k;
        ok[k] = false;
        if (e < N_EDGES) {
            srcv[k] = ei[e];
            dstv[k] = ei[N_EDGES + e];
            ok[k] = (unsigned)srcv[k] < (unsigned)N_NODES &&
                    (unsigned)dstv[k] < (unsigned)N_NODES;
        }
    }
#pragma unroll
    for (int k = 0; k < FILL_EPT; k++)
        if (ok[k]) posv[k] = g_rowptr[dstv[k]] + atomicAdd(&g_cnt[dstv[k]], 1);
#pragma unroll
    for (int k = 0; k < FILL_EPT; k++)
        if (ok[k] && (unsigned)posv[k] < (unsigned)N_EDGES) {
            uint2 rec;
            rec.x = (uint32_t)srcv[k];
            rec.y = __float_as_uint(g_dinv[srcv[k]] * g_dinv[dstv[k]]);
            g_edge[posv[k]] = rec;
        }
}

// ---------------- fused warp-local aggregation + HMMA GEMM -------------------
// Block = 16 nodes, 8 warps; warp = 2 nodes = 16 GEMM rows (r = n*8+t).
// Phase A: warp-private CSR gather (no block barrier) -> fp16 smem tile.
// Phase B: __syncwarp, 16x64 HMMA GEMM with pre-packed W fragments.
// in and out MUST be distinct buffers.
template <int K, bool CLEANUP>
__global__ void __launch_bounds__(256) fused_agg_gemm_kernel(
    const uint4* __restrict__ in, const uint2* __restrict__ Wf,
    const float* __restrict__ bias, __half* __restrict__ out) {
    constexpr int NU  = K / 32;          // uint4 per lane per node-row
    constexpr int C2  = K / 2;           // half2 per GEMM row
    constexpr int PAD = (K == 64) ? 36 : 20;
    constexpr int KS  = K / 16;
    constexpr int TSH = (K == 64) ? 5 : 4;   // f>>TSH = t
    __shared__ uint32_t As[8 * 16 * PAD];

    int tid = threadIdx.x, lane = tid & 31, warp = tid >> 5;

    if (CLEANUP) {   // re-zero deg/cnt for the next replay (post fill_csr)
        int gi = blockIdx.x * 256 + tid;
        if (gi < N_NODES) { g_deg[gi] = 0; g_cnt[gi] = 0; }
    }

    uint32_t* Aw = As + warp * 16 * PAD;

    // ---- phase A: gather 2 nodes ----
#pragma unroll
    for (int ln = 0; ln < 2; ln++) {
        int n = blockIdx.x * 16 + warp * 2 + ln;
        float dv = g_dinv[n];
        float dv2 = dv * dv;
        float2 acc[NU * 4];
#pragma unroll
        for (int u = 0; u < NU; u++) {
            uint4 v = __ldg(&in[(size_t)n * (NU * 32) + u * 32 + lane]);
            uint32_t uu[4] = {v.x, v.y, v.z, v.w};
#pragma unroll
            for (int q = 0; q < 4; q++) {
                float2 f = u2f(uu[q]);
                acc[u * 4 + q].x = dv2 * f.x;
                acc[u * 4 + q].y = dv2 * f.y;
            }
        }
        int s = g_rowptr[n], e2 = g_rowptr[n + 1];
        // software-pipelined edge-chunk records: prefetch next chunk early
        uint2 rec = make_uint2(0u, 0u);
        if (s + lane < e2) rec = __ldg(&g_edge[s + lane]);
        for (int base = s; base < e2; base += 32) {
            int sl = (int)rec.x;
            float nl = __uint_as_float(rec.y);
            if (base + lane >= e2) nl = 0.f;   // lanes past end contribute 0
            // prefetch next chunk before consuming this one
            int nidx = base + 32 + lane;
            if (nidx < e2) rec = __ldg(&g_edge[nidx]);
            int cnt = min(32, e2 - base);
            int j = 0;
            if (K == 32) {
                for (; j + 4 <= cnt; j += 4) {   // 4-edge unroll (MLP=4)
                    int s0 = __shfl_sync(0xffffffffu, sl, j);
                    int s1 = __shfl_sync(0xffffffffu, sl, j + 1);
                    int s2 = __shfl_sync(0xffffffffu, sl, j + 2);
                    int s3 = __shfl_sync(0xffffffffu, sl, j + 3);
                    float w0 = __shfl_sync(0xffffffffu, nl, j);
                    float w1 = __shfl_sync(0xffffffffu, nl, j + 1);
                    float w2 = __shfl_sync(0xffffffffu, nl, j + 2);
                    float w3 = __shfl_sync(0xffffffffu, nl, j + 3);
                    uint4 v0 = __ldg(&in[(size_t)s0 * 32 + lane]);
                    uint4 v1 = __ldg(&in[(size_t)s1 * 32 + lane]);
                    uint4 v2 = __ldg(&in[(size_t)s2 * 32 + lane]);
                    uint4 v3 = __ldg(&in[(size_t)s3 * 32 + lane]);
                    uint32_t u0[4] = {v0.x, v0.y, v0.z, v0.w};
                    uint32_t u1[4] = {v1.x, v1.y, v1.z, v1.w};
                    uint32_t u2[4] = {v2.x, v2.y, v2.z, v2.w};
                    uint32_t u3[4] = {v3.x, v3.y, v3.z, v3.w};
#pragma unroll
                    for (int q = 0; q < 4; q++) {
                        float2 f0 = u2f(u0[q]), f1 = u2f(u1[q]);
                        float2 f2 = u2f(u2[q]), f3 = u2f(u3[q]);
                        acc[q].x = fmaf(w0, f0.x, acc[q].x); acc[q].y = fmaf(w0, f0.y, acc[q].y);
                        acc[q].x = fmaf(w1, f1.x, acc[q].x); acc[q].y = fmaf(w1, f1.y, acc[q].y);
                        acc[q].x = fmaf(w2, f2.x, acc[q].x); acc[q].y = fmaf(w2, f2.y, acc[q].y);
                        acc[q].x = fmaf(w3, f3.x, acc[q].x); acc[q].y = fmaf(w3, f3.y, acc[q].y);
                    }
                }
            } else {
                for (; j + 2 <= cnt; j += 2) {   // 2-edge unroll (4 loads in flight)
                    int s0 = __shfl_sync(0xffffffffu, sl, j);
                    int s1 = __shfl_sync(0xffffffffu, sl, j + 1);
                    float w0 = __shfl_sync(0xffffffffu, nl, j);
                    float w1 = __shfl_sync(0xffffffffu, nl, j + 1);
                    uint4 va[NU], vb[NU];
#pragma unroll
                    for (int u = 0; u < NU; u++) {
                        va[u] = __ldg(&in[(size_t)s0 * (NU * 32) + u * 32 + lane]);
                        vb[u] = __ldg(&in[(size_t)s1 * (NU * 32) + u * 32 + lane]);
                    }
#pragma unroll
                    for (int u = 0; u < NU; u++) {
                        uint32_t ua[4] = {va[u].x, va[u].y, va[u].z, va[u].w};
                        uint32_t ub[4] = {vb[u].x, vb[u].y, vb[u].z, vb[u].w};
#pragma unroll
                        for (int q = 0; q < 4; q++) {
                            float2 fa = u2f(ua[q]), fb = u2f(ub[q]);
                            acc[u * 4 + q].x = fmaf(w0, fa.x, acc[u * 4 + q].x);
                            acc[u * 4 + q].y = fmaf(w0, fa.y, acc[u * 4 + q].y);
                            acc[u * 4 + q].x = fmaf(w1, fb.x, acc[u * 4 + q].x);
                            acc[u * 4 + q].y = fmaf(w1, fb.y, acc[u * 4 + q].y);
                        }
                    }
                }
            }
            for (; j < cnt; j++) {
                int src  = __shfl_sync(0xffffffffu, sl, j);
                float wt = __shfl_sync(0xffffffffu, nl, j);
#pragma unroll
                for (int u = 0; u < NU; u++) {
                    uint4 v = __ldg(&in[(size_t)src * (NU * 32) + u * 32 + lane]);
                    uint32_t uu[4] = {v.x, v.y, v.z, v.w};
#pragma unroll
                    for (int q = 0; q < 4; q++) {
                        float2 f = u2f(uu[q]);
                        acc[u * 4 + q].x = fmaf(wt, f.x, acc[u * 4 + q].x);
                        acc[u * 4 + q].y = fmaf(wt, f.y, acc[u * 4 + q].y);
                    }
                }
            }
        }
        // store to warp-private smem tile (uint4 = 4 consecutive half2)
#pragma unroll
        for (int u = 0; u < NU; u++) {
            int f = (lane + u * 32) * 4;
            int t = f >> TSH;
            int c2 = f & (C2 - 1);
            uint4 o;
            o.x = f2u(acc[u * 4 + 0].x, acc[u * 4 + 0].y);
            o.y = f2u(acc[u * 4 + 1].x, acc[u * 4 + 1].y);
            o.z = f2u(acc[u * 4 + 2].x, acc[u * 4 + 2].y);
            o.w = f2u(acc[u * 4 + 3].x, acc[u * 4 + 3].y);
            *(uint4*)(Aw + (ln * 8 + t) * PAD + c2) = o;
        }
    }
    __syncwarp();

    // ---- phase B: 16x64 HMMA GEMM ----
    int lq = lane >> 2, lr = lane & 3;
    float acc2[8][4];
#pragma unroll
    for (int j = 0; j < 8; j++)
#pragma unroll
        for (int q = 0; q < 4; q++) acc2[j][q] = 0.f;

#pragma unroll
    for (int ks = 0; ks < KS; ks++) {
        int c2a = ks * 8 + lr;
        uint32_t a0 = Aw[lq * PAD + c2a];
        uint32_t a1 = Aw[(lq + 8) * PAD + c2a];
        uint32_t a2 = Aw[lq * PAD + c2a + 4];
        uint32_t a3 = Aw[(lq + 8) * PAD + c2a + 4];
#pragma unroll
        for (int j = 0; j < 8; j++) {
            uint2 bf = __ldg(&Wf[ks * 256 + j * 32 + lane]);
            asm volatile(
                "mma.sync.aligned.m16n8k16.row.col.f32.f16.f16.f32 "
                "{%0,%1,%2,%3}, {%4,%5,%6,%7}, {%8,%9}, {%0,%1,%2,%3};"
                : "+f"(acc2[j][0]), "+f"(acc2[j][1]),
                  "+f"(acc2[j][2]), "+f"(acc2[j][3])
                : "r"(a0), "r"(a1), "r"(a2), "r"(a3),
                  "r"(bf.x), "r"(bf.y));
        }
    }

    // epilogue: bias + relu, fp16 store
    size_t row0 = (size_t)blockIdx.x * 128 + warp * 16;
#pragma unroll
    for (int j = 0; j < 8; j++) {
        int c = j * 8 + lr * 2;
        float bx = bias[c], by = bias[c + 1];
        float ox = fmaxf(acc2[j][0] + bx, 0.f);
        float oy = fmaxf(acc2[j][1] + by, 0.f);
        *(__half2*)(out + (row0 + lq) * 64 + c) = __floats2half2_rn(ox, oy);
        float oz = fmaxf(acc2[j][2] + bx, 0.f);
        float ow = fmaxf(acc2[j][3] + by, 0.f);
        *(__half2*)(out + (row0 + lq + 8) * 64 + c) = __floats2half2_rn(oz, ow);
    }
}

// ---------------- pooling: out[b, c, t] (max) and [b, 64+c, t] (mean) --------
template <bool FIRST>
__global__ void __launch_bounds__(256) pool_all_kernel(const __half* __restrict__ h,
                                                       float* __restrict__ out) {
    int b = blockIdx.x, t = blockIdx.y;
    int tid = threadIdx.x;
    int c2 = tid & 31, g = tid >> 5;  // 8 groups
    const __half2* hp = (const __half2*)(h + ((size_t)b * NPG * 8 + t) * 64) + c2;
    float2 mx = make_float2(-1e30f, -1e30f);
    float2 sm = make_float2(0.f, 0.f);
    for (int i = g; i < NPG; i += 8) {
        float2 f = __half22float2(hp[(size_t)i * 256]);
        mx.x = fmaxf(mx.x, f.x); mx.y = fmaxf(mx.y, f.y);
        sm.x += f.x; sm.y += f.y;
    }
    __shared__ float2 smx[8][32], ssm[8][32];
    smx[g][c2] = mx; ssm[g][c2] = sm;
    __syncthreads();
    if (tid < 32) {
        float2 m = smx[0][tid], s = ssm[0][tid];
#pragma unroll
        for (int k = 1; k < 8; k++) {
            m.x = fmaxf(m.x, smx[k][tid].x); m.y = fmaxf(m.y, smx[k][tid].y);
            s.x += ssm[k][tid].x;            s.y += ssm[k][tid].y;
        }
        s.x *= (1.f / (float)NPG); s.y *= (1.f / (float)NPG);
        int c0 = 2 * tid;
        float* ob = out + b * 1024;
        if (FIRST) {
            ob[c0 * 8 + t]        = m.x; ob[(c0 + 1) * 8 + t]  = m.y;
            ob[(64 + c0) * 8 + t] = s.x; ob[(65 + c0) * 8 + t] = s.y;
        } else {
            ob[c0 * 8 + t]        += m.x; ob[(c0 + 1) * 8 + t]  += m.y;
            ob[(64 + c0) * 8 + t] += s.x; ob[(65 + c0) * 8 + t] += s.y;
        }
    }
}

// ---------------- launch -----------------------------------------------------
extern "C" void kernel_launch(void* const* d_in, const int* in_sizes, int n_in,
                              void* d_out, int out_size) {
    const float* x  = (const float*)d_in[0];
    const int*   ei = (const int*)d_in[1];     // int32 [2, E]
    const float* W1 = (const float*)d_in[3];
    const float* b1 = (const float*)d_in[4];
    const float* W2 = (const float*)d_in[5];
    const float* b2 = (const float*)d_in[6];
    const float* W3 = (const float*)d_in[7];
    const float* b3 = (const float*)d_in[8];
    float* out = (float*)d_out;

    __half *xh, *hA, *hB;
    uint2 *wf1, *wf2, *wf3;
    cudaGetSymbolAddress((void**)&xh,  g_xh);
    cudaGetSymbolAddress((void**)&hA,  g_hA);
    cudaGetSymbolAddress((void**)&hB,  g_hB);
    cudaGetSymbolAddress((void**)&wf1, g_Wf1);
    cudaGetSymbolAddress((void**)&wf2, g_Wf2);
    cudaGetSymbolAddress((void**)&wf3, g_Wf3);

    // setup (deg/cnt zero: module load on call 1, fused<32> thereafter)
    setup_all_kernel<<<(N_NODES * C_IN + 255) / 256, 256>>>(x, ei, W1, W2, W3);
    scan_part_kernel<<<SCAN_NBLK, 256>>>();
    scan_apply_kernel<<<(N_NODES + 1023) / 1024, 1024>>>();
    fill_csr_kernel<<<(N_EDGES + 256 * FILL_EPT - 1) / (256 * FILL_EPT), 256>>>(ei);

    const int FUSE_GRID = N_NODES / 16;   // 3125 blocks, 16 nodes, 8 warps
    dim3 pool_grid(NB, NT);

    // layer 1: xh -> hA  (+ deg/cnt cleanup for next replay)
    fused_agg_gemm_kernel<32, true><<<FUSE_GRID, 256>>>((const uint4*)xh, wf1, b1, hA);
    pool_all_kernel<true><<<pool_grid, 256>>>(hA, out);
    // layer 2: hA -> hB
    fused_agg_gemm_kernel<64, false><<<FUSE_GRID, 256>>>((const uint4*)hA, wf2, b2, hB);
    pool_all_kernel<false><<<pool_grid, 256>>>(hB, out);
    // layer 3: hB -> hA
    fused_agg_gemm_kernel<64, false><<<FUSE_GRID, 256>>>((const uint4*)hB, wf3, b3, hA);
    pool_all_kernel<false><<<pool_grid, 256>>>(hA, out);
}

// round 17
// speedup vs baseline: 1.0347x; 1.0347x over previous
#include <cuda_runtime.h>
#include <cuda_fp16.h>
#include <math.h>
#include <stdint.h>

#define N_NODES 50000
#define N_EDGES 800000
#define NB      250
#define NT      8
#define C_IN    32
#define C_OUT   64
#define NPG     200   // nodes per graph (contiguous)
#define SCAN_NBLK ((N_NODES + 255) / 256)   // 196

// ---------------- scratch (static device globals; no allocation) -------------
__device__ __half g_xh[(size_t)N_NODES * NT * C_IN];    // [n][t][c] fp16 (row 512B)
__device__ __half g_hA[(size_t)N_NODES * NT * C_OUT];   // layer-1 out
__device__ __half g_hB[(size_t)N_NODES * NT * C_OUT];   // layer-2 out
__device__ __half g_hC[(size_t)N_NODES * NT * C_OUT];   // layer-3 out
__device__ uint2  g_Wf1[2 * 8 * 32];   // W1 MMA fragments [ks][j][lane]
__device__ uint2  g_Wf2[4 * 8 * 32];
__device__ uint2  g_Wf3[4 * 8 * 32];
__device__ int    g_deg[N_NODES];      // zero-init at load; re-zeroed by fused<32>
__device__ int    g_cnt[N_NODES];
__device__ int    g_rowptr[N_NODES + 1];
__device__ int    g_bsum[SCAN_NBLK];
__device__ float  g_dinv[N_NODES];
__device__ uint2  g_edge[N_EDGES];     // {src, norm bits}

// ---------------- helpers ----------------------------------------------------
__device__ __forceinline__ float2 u2f(uint32_t u) {
    __half2 h = *(__half2*)&u;
    return __half22float2(h);
}
__device__ __forceinline__ uint32_t f2u(float a, float b) {
    __half2 h = __floats2half2_rn(a, b);
    return *(uint32_t*)&h;
}

// ---------------- setup: W frags + transpose x + count_deg -------------------
__device__ __forceinline__ void wfrag_store(uint2* Wf, const float* W, int rem) {
    int ks = rem >> 8, j = (rem >> 5) & 7, lane = rem & 31;
    int lq = lane >> 2, lr = lane & 3;
    int n = j * 8 + lq;
    int kb = ks * 16 + lr * 2;
    uint2 f;
    f.x = f2u(W[kb * 64 + n],       W[(kb + 1) * 64 + n]);
    f.y = f2u(W[(kb + 8) * 64 + n], W[(kb + 9) * 64 + n]);
    Wf[rem] = f;
}

__global__ void setup_all_kernel(const float* __restrict__ x,
                                 const int* __restrict__ ei,
                                 const float* __restrict__ W1,
                                 const float* __restrict__ W2,
                                 const float* __restrict__ W3) {
    int i = blockIdx.x * blockDim.x + threadIdx.x;
    if (i < 512)                    wfrag_store(g_Wf1, W1, i);
    else if (i >= 1024 && i < 2048) wfrag_store(g_Wf2, W2, i - 1024);
    else if (i >= 2048 && i < 3072) wfrag_store(g_Wf3, W3, i - 2048);
    if (i < N_EDGES) {
        int dst = ei[N_EDGES + i];
        if ((unsigned)dst < (unsigned)N_NODES)
            atomicAdd(&g_deg[dst], 1);
    }
    if (i >= N_NODES * C_IN) return;
    int n = i / C_IN, c = i % C_IN;
    const float4* p = (const float4*)(x + (size_t)i * NT);
    float4 a = p[0], b4 = p[1];
    float v[8] = {a.x, a.y, a.z, a.w, b4.x, b4.y, b4.z, b4.w};
#pragma unroll
    for (int t = 0; t < NT; t++)
        g_xh[(size_t)n * (NT * C_IN) + t * C_IN + c] = __float2half_rn(v[t]);
}

// ---------------- parallel scan ---------------------------------------------
__global__ void __launch_bounds__(256) scan_part_kernel() {
    __shared__ int ws[8];
    int b = blockIdx.x, tid = threadIdx.x;
    int i = b * 256 + tid;
    int lane = tid & 31, wid = tid >> 5;
    int v = (i < N_NODES) ? g_deg[i] : 0;
    if (i < N_NODES) g_dinv[i] = rsqrtf((float)(v + 1));  // +1 self loop
    int x = v;
#pragma unroll
    for (int off = 1; off < 32; off <<= 1) {
        int y = __shfl_up_sync(0xffffffffu, x, off);
        if (lane >= off) x += y;
    }
    if (lane == 31) ws[wid] = x;
    __syncthreads();
    if (tid < 8) {
        int s = ws[tid];
#pragma unroll
        for (int off = 1; off < 8; off <<= 1) {
            int y = __shfl_up_sync(0x000000ffu, s, off);
            if (tid >= off) s += y;
        }
        ws[tid] = s;
    }
    __syncthreads();
    int woff = wid ? ws[wid - 1] : 0;
    if (i < N_NODES) g_rowptr[i] = woff + x - v;   // local exclusive
    if (tid == 0) g_bsum[b] = ws[7];
}

// grid 49 x 1024: each block redundantly scans the 196 block sums, then
// applies offsets to its range. Cross-warp smem edges use __syncthreads.
__global__ void __launch_bounds__(1024) scan_apply_kernel() {
    __shared__ int boff[256];
    __shared__ int wsum[8];
    int tid = threadIdx.x;
    int lane = tid & 31, wid = tid >> 5;
    int v = 0, x = 0;
    if (tid < 256) {
        v = (tid < SCAN_NBLK) ? g_bsum[tid] : 0;
        x = v;
#pragma unroll
        for (int off = 1; off < 32; off <<= 1) {
            int y = __shfl_up_sync(0xffffffffu, x, off);
            if (lane >= off) x += y;
        }
        if (lane == 31) wsum[wid] = x;
    }
    __syncthreads();
    if (tid == 0) {
        int run = 0;
#pragma unroll
        for (int w = 0; w < 8; w++) { int s = wsum[w]; wsum[w] = run; run += s; }
        if (blockIdx.x == 0) g_rowptr[N_NODES] = run;
    }
    __syncthreads();
    if (tid < 256)
        boff[tid] = wsum[wid] + x - v;
    __syncthreads();
    int i = blockIdx.x * 1024 + tid;
    if (i < N_NODES) g_rowptr[i] += boff[i >> 8];
}

// R15 form: 1 edge/thread (throughput-bound at LTS; ILP batching regressed it).
__global__ void fill_csr_kernel(const int* __restrict__ ei) {
    int e = blockIdx.x * blockDim.x + threadIdx.x;
    if (e >= N_EDGES) return;
    int src = ei[e];
    int dst = ei[N_EDGES + e];
    if ((unsigned)src >= (unsigned)N_NODES ||
        (unsigned)dst >= (unsigned)N_NODES) return;
    int pos = g_rowptr[dst] + atomicAdd(&g_cnt[dst], 1);
    if ((unsigned)pos < (unsigned)N_EDGES) {
        uint2 rec;
        rec.x = (uint32_t)src;
        rec.y = __float_as_uint(g_dinv[src] * g_dinv[dst]);
        g_edge[pos] = rec;
    }
}

// ---------------- fused warp-local aggregation + HMMA GEMM -------------------
// Block = 16 nodes, 8 warps; warp = 2 nodes = 16 GEMM rows (r = n*8+t).
// Phase A: warp-private CSR gather (no block barrier) -> fp16 smem tile.
// Phase B: __syncwarp, 16x64 HMMA GEMM with pre-packed W fragments.
// in and out MUST be distinct buffers. (R15 form — no prefetch.)
template <int K, bool CLEANUP>
__global__ void __launch_bounds__(256) fused_agg_gemm_kernel(
    const uint4* __restrict__ in, const uint2* __restrict__ Wf,
    const float* __restrict__ bias, __half* __restrict__ out) {
    constexpr int NU  = K / 32;          // uint4 per lane per node-row
    constexpr int C2  = K / 2;           // half2 per GEMM row
    constexpr int PAD = (K == 64) ? 36 : 20;
    constexpr int KS  = K / 16;
    constexpr int TSH = (K == 64) ? 5 : 4;   // f>>TSH = t
    __shared__ uint32_t As[8 * 16 * PAD];

    int tid = threadIdx.x, lane = tid & 31, warp = tid >> 5;

    if (CLEANUP) {   // re-zero deg/cnt for the next replay (post fill_csr)
        int gi = blockIdx.x * 256 + tid;
        if (gi < N_NODES) { g_deg[gi] = 0; g_cnt[gi] = 0; }
    }

    uint32_t* Aw = As + warp * 16 * PAD;

    // ---- phase A: gather 2 nodes ----
#pragma unroll
    for (int ln = 0; ln < 2; ln++) {
        int n = blockIdx.x * 16 + warp * 2 + ln;
        float dv = g_dinv[n];
        float dv2 = dv * dv;
        float2 acc[NU * 4];
#pragma unroll
        for (int u = 0; u < NU; u++) {
            uint4 v = __ldg(&in[(size_t)n * (NU * 32) + u * 32 + lane]);
            uint32_t uu[4] = {v.x, v.y, v.z, v.w};
#pragma unroll
            for (int q = 0; q < 4; q++) {
                float2 f = u2f(uu[q]);
                acc[u * 4 + q].x = dv2 * f.x;
                acc[u * 4 + q].y = dv2 * f.y;
            }
        }
        int s = g_rowptr[n], e2 = g_rowptr[n + 1];
        for (int base = s; base < e2; base += 32) {
            int idx = base + lane;
            int sl = 0; float nl = 0.f;
            if (idx < e2) {
                uint2 rec = __ldg(&g_edge[idx]);
                sl = (int)rec.x; nl = __uint_as_float(rec.y);
            }
            int cnt = min(32, e2 - base);
            int j = 0;
            if (K == 32) {
                for (; j + 4 <= cnt; j += 4) {   // 4-edge unroll (MLP=4)
                    int s0 = __shfl_sync(0xffffffffu, sl, j);
                    int s1 = __shfl_sync(0xffffffffu, sl, j + 1);
                    int s2 = __shfl_sync(0xffffffffu, sl, j + 2);
                    int s3 = __shfl_sync(0xffffffffu, sl, j + 3);
                    float w0 = __shfl_sync(0xffffffffu, nl, j);
                    float w1 = __shfl_sync(0xffffffffu, nl, j + 1);
                    float w2 = __shfl_sync(0xffffffffu, nl, j + 2);
                    float w3 = __shfl_sync(0xffffffffu, nl, j + 3);
                    uint4 v0 = __ldg(&in[(size_t)s0 * 32 + lane]);
                    uint4 v1 = __ldg(&in[(size_t)s1 * 32 + lane]);
                    uint4 v2 = __ldg(&in[(size_t)s2 * 32 + lane]);
                    uint4 v3 = __ldg(&in[(size_t)s3 * 32 + lane]);
                    uint32_t u0[4] = {v0.x, v0.y, v0.z, v0.w};
                    uint32_t u1[4] = {v1.x, v1.y, v1.z, v1.w};
                    uint32_t u2[4] = {v2.x, v2.y, v2.z, v2.w};
                    uint32_t u3[4] = {v3.x, v3.y, v3.z, v3.w};
#pragma unroll
                    for (int q = 0; q < 4; q++) {
                        float2 f0 = u2f(u0[q]), f1 = u2f(u1[q]);
                        float2 f2 = u2f(u2[q]), f3 = u2f(u3[q]);
                        acc[q].x = fmaf(w0, f0.x, acc[q].x); acc[q].y = fmaf(w0, f0.y, acc[q].y);
                        acc[q].x = fmaf(w1, f1.x, acc[q].x); acc[q].y = fmaf(w1, f1.y, acc[q].y);
                        acc[q].x = fmaf(w2, f2.x, acc[q].x); acc[q].y = fmaf(w2, f2.y, acc[q].y);
                        acc[q].x = fmaf(w3, f3.x, acc[q].x); acc[q].y = fmaf(w3, f3.y, acc[q].y);
                    }
                }
            } else {
                for (; j + 2 <= cnt; j += 2) {   // 2-edge unroll (4 loads in flight)
                    int s0 = __shfl_sync(0xffffffffu, sl, j);
                    int s1 = __shfl_sync(0xffffffffu, sl, j + 1);
                    float w0 = __shfl_sync(0xffffffffu, nl, j);
                    float w1 = __shfl_sync(0xffffffffu, nl, j + 1);
                    uint4 va[NU], vb[NU];
#pragma unroll
                    for (int u = 0; u < NU; u++) {
                        va[u] = __ldg(&in[(size_t)s0 * (NU * 32) + u * 32 + lane]);
                        vb[u] = __ldg(&in[(size_t)s1 * (NU * 32) + u * 32 + lane]);
                    }
#pragma unroll
                    for (int u = 0; u < NU; u++) {
                        uint32_t ua[4] = {va[u].x, va[u].y, va[u].z, va[u].w};
                        uint32_t ub[4] = {vb[u].x, vb[u].y, vb[u].z, vb[u].w};
#pragma unroll
                        for (int q = 0; q < 4; q++) {
                            float2 fa = u2f(ua[q]), fb = u2f(ub[q]);
                            acc[u * 4 + q].x = fmaf(w0, fa.x, acc[u * 4 + q].x);
                            acc[u * 4 + q].y = fmaf(w0, fa.y, acc[u * 4 + q].y);
                            acc[u * 4 + q].x = fmaf(w1, fb.x, acc[u * 4 + q].x);
                            acc[u * 4 + q].y = fmaf(w1, fb.y, acc[u * 4 + q].y);
                        }
                    }
                }
            }
            for (; j < cnt; j++) {
                int src  = __shfl_sync(0xffffffffu, sl, j);
                float wt = __shfl_sync(0xffffffffu, nl, j);
#pragma unroll
                for (int u = 0; u < NU; u++) {
                    uint4 v = __ldg(&in[(size_t)src * (NU * 32) + u * 32 + lane]);
                    uint32_t uu[4] = {v.x, v.y, v.z, v.w};
#pragma unroll
                    for (int q = 0; q < 4; q++) {
                        float2 f = u2f(uu[q]);
                        acc[u * 4 + q].x = fmaf(wt, f.x, acc[u * 4 + q].x);
                        acc[u * 4 + q].y = fmaf(wt, f.y, acc[u * 4 + q].y);
                    }
                }
            }
        }
        // store to warp-private smem tile (uint4 = 4 consecutive half2)
#pragma unroll
        for (int u = 0; u < NU; u++) {
            int f = (lane + u * 32) * 4;
            int t = f >> TSH;
            int c2 = f & (C2 - 1);
            uint4 o;
            o.x = f2u(acc[u * 4 + 0].x, acc[u * 4 + 0].y);
            o.y = f2u(acc[u * 4 + 1].x, acc[u * 4 + 1].y);
            o.z = f2u(acc[u * 4 + 2].x, acc[u * 4 + 2].y);
            o.w = f2u(acc[u * 4 + 3].x, acc[u * 4 + 3].y);
            *(uint4*)(Aw + (ln * 8 + t) * PAD + c2) = o;
        }
    }
    __syncwarp();

    // ---- phase B: 16x64 HMMA GEMM ----
    int lq = lane >> 2, lr = lane & 3;
    float acc2[8][4];
#pragma unroll
    for (int j = 0; j < 8; j++)
#pragma unroll
        for (int q = 0; q < 4; q++) acc2[j][q] = 0.f;

#pragma unroll
    for (int ks = 0; ks < KS; ks++) {
        int c2a = ks * 8 + lr;
        uint32_t a0 = Aw[lq * PAD + c2a];
        uint32_t a1 = Aw[(lq + 8) * PAD + c2a];
        uint32_t a2 = Aw[lq * PAD + c2a + 4];
        uint32_t a3 = Aw[(lq + 8) * PAD + c2a + 4];
#pragma unroll
        for (int j = 0; j < 8; j++) {
            uint2 bf = __ldg(&Wf[ks * 256 + j * 32 + lane]);
            asm volatile(
                "mma.sync.aligned.m16n8k16.row.col.f32.f16.f16.f32 "
                "{%0,%1,%2,%3}, {%4,%5,%6,%7}, {%8,%9}, {%0,%1,%2,%3};"
                : "+f"(acc2[j][0]), "+f"(acc2[j][1]),
                  "+f"(acc2[j][2]), "+f"(acc2[j][3])
                : "r"(a0), "r"(a1), "r"(a2), "r"(a3),
                  "r"(bf.x), "r"(bf.y));
        }
    }

    // epilogue: bias + relu, fp16 store
    size_t row0 = (size_t)blockIdx.x * 128 + warp * 16;
#pragma unroll
    for (int j = 0; j < 8; j++) {
        int c = j * 8 + lr * 2;
        float bx = bias[c], by = bias[c + 1];
        float ox = fmaxf(acc2[j][0] + bx, 0.f);
        float oy = fmaxf(acc2[j][1] + by, 0.f);
        *(__half2*)(out + (row0 + lq) * 64 + c) = __floats2half2_rn(ox, oy);
        float oz = fmaxf(acc2[j][2] + bx, 0.f);
        float ow = fmaxf(acc2[j][3] + by, 0.f);
        *(__half2*)(out + (row0 + lq + 8) * 64 + c) = __floats2half2_rn(oz, ow);
    }
}

// ---------------- pooling: all 3 layers in one pass --------------------------
// out[b, c, t] = max1+max2+max3; out[b, 64+c, t] = mean1+mean2+mean3.
// Same accumulation order as the old =, +=, += sequence (bit-identical).
__global__ void __launch_bounds__(256) pool3_kernel(const __half* __restrict__ h1,
                                                    const __half* __restrict__ h2,
                                                    const __half* __restrict__ h3,
                                                    float* __restrict__ out) {
    int b = blockIdx.x, t = blockIdx.y;
    int tid = threadIdx.x;
    int c2 = tid & 31, g = tid >> 5;  // 8 groups
    size_t off = ((size_t)b * NPG * 8 + t) * 32 + c2;   // in half2 units
    const __half2* p1 = (const __half2*)h1 + off;
    const __half2* p2 = (const __half2*)h2 + off;
    const __half2* p3 = (const __half2*)h3 + off;
    float2 mx1 = make_float2(-1e30f, -1e30f), sm1 = make_float2(0.f, 0.f);
    float2 mx2 = mx1, sm2 = sm1;
    float2 mx3 = mx1, sm3 = sm1;
    for (int i = g; i < NPG; i += 8) {
        float2 f1 = __half22float2(p1[(size_t)i * 256]);
        float2 f2 = __half22float2(p2[(size_t)i * 256]);
        float2 f3 = __half22float2(p3[(size_t)i * 256]);
        mx1.x = fmaxf(mx1.x, f1.x); mx1.y = fmaxf(mx1.y, f1.y);
        sm1.x += f1.x; sm1.y += f1.y;
        mx2.x = fmaxf(mx2.x, f2.x); mx2.y = fmaxf(mx2.y, f2.y);
        sm2.x += f2.x; sm2.y += f2.y;
        mx3.x = fmaxf(mx3.x, f3.x); mx3.y = fmaxf(mx3.y, f3.y);
        sm3.x += f3.x; sm3.y += f3.y;
    }
    __shared__ float2 smx[3][8][32], ssm[3][8][32];
    smx[0][g][c2] = mx1; ssm[0][g][c2] = sm1;
    smx[1][g][c2] = mx2; ssm[1][g][c2] = sm2;
    smx[2][g][c2] = mx3; ssm[2][g][c2] = sm3;
    __syncthreads();
    if (tid < 32) {
        float2 m[3], s[3];
#pragma unroll
        for (int l = 0; l < 3; l++) {
            m[l] = smx[l][0][tid]; s[l] = ssm[l][0][tid];
#pragma unroll
            for (int k = 1; k < 8; k++) {
                m[l].x = fmaxf(m[l].x, smx[l][k][tid].x);
                m[l].y = fmaxf(m[l].y, smx[l][k][tid].y);
                s[l].x += ssm[l][k][tid].x;
                s[l].y += ssm[l][k][tid].y;
            }
            s[l].x *= (1.f / (float)NPG);
            s[l].y *= (1.f / (float)NPG);
        }
        int c0 = 2 * tid;
        float* ob = out + b * 1024;
        ob[c0 * 8 + t]        = (m[0].x + m[1].x) + m[2].x;
        ob[(c0 + 1) * 8 + t]  = (m[0].y + m[1].y) + m[2].y;
        ob[(64 + c0) * 8 + t] = (s[0].x + s[1].x) + s[2].x;
        ob[(65 + c0) * 8 + t] = (s[0].y + s[1].y) + s[2].y;
    }
}

// ---------------- launch -----------------------------------------------------
extern "C" void kernel_launch(void* const* d_in, const int* in_sizes, int n_in,
                              void* d_out, int out_size) {
    const float* x  = (const float*)d_in[0];
    const int*   ei = (const int*)d_in[1];     // int32 [2, E]
    const float* W1 = (const float*)d_in[3];
    const float* b1 = (const float*)d_in[4];
    const float* W2 = (const float*)d_in[5];
    const float* b2 = (const float*)d_in[6];
    const float* W3 = (const float*)d_in[7];
    const float* b3 = (const float*)d_in[8];
    float* out = (float*)d_out;

    __half *xh, *hA, *hB, *hC;
    uint2 *wf1, *wf2, *wf3;
    cudaGetSymbolAddress((void**)&xh,  g_xh);
    cudaGetSymbolAddress((void**)&hA,  g_hA);
    cudaGetSymbolAddress((void**)&hB,  g_hB);
    cudaGetSymbolAddress((void**)&hC,  g_hC);
    cudaGetSymbolAddress((void**)&wf1, g_Wf1);
    cudaGetSymbolAddress((void**)&wf2, g_Wf2);
    cudaGetSymbolAddress((void**)&wf3, g_Wf3);

    // setup (deg/cnt zero: module load on call 1, fused<32> thereafter)
    setup_all_kernel<<<(N_NODES * C_IN + 255) / 256, 256>>>(x, ei, W1, W2, W3);
    scan_part_kernel<<<SCAN_NBLK, 256>>>();
    scan_apply_kernel<<<(N_NODES + 1023) / 1024, 1024>>>();
    fill_csr_kernel<<<(N_EDGES + 255) / 256, 256>>>(ei);

    const int FUSE_GRID = N_NODES / 16;   // 3125 blocks, 16 nodes, 8 warps
    dim3 pool_grid(NB, NT);

    // layer 1: xh -> hA  (+ deg/cnt cleanup for next replay)
    fused_agg_gemm_kernel<32, true><<<FUSE_GRID, 256>>>((const uint4*)xh, wf1, b1, hA);
    // layer 2: hA -> hB
    fused_agg_gemm_kernel<64, false><<<FUSE_GRID, 256>>>((const uint4*)hA, wf2, b2, hB);
    // layer 3: hB -> hC
    fused_agg_gemm_kernel<64, false><<<FUSE_GRID, 256>>>((const uint4*)hB, wf3, b3, hC);
    // single pool over all three layers
    pool3_kernel<<<pool_grid, 256>>>(hA, hB, hC, out);
}